// round 9
// baseline (speedup 1.0000x reference)
#include <cuda_runtime.h>
#include <cuda_fp16.h>
#include <math.h>
#include <stdint.h>

#define NH     4096
#define K2     8192
#define GRIDB  128          // blocks (<= 148 SMs -> co-resident, sync safe)
#define TPB    512          // 16 warps
#define ROWS_PB 32
#define SL_STRIDE 32        // pad slice counters to separate 128B lines

// ---------------- persistent device scratch (no allocations) ----------------
__device__ __half g_W1p[(size_t)NH * NH];   // fp16 f_W1, fragment-major
__device__ __half g_W2p[(size_t)NH * NH];   // fp16 f_W2, fragment-major
__device__ __half g_vh[2 * NH];             // current ODE input vector v (fp16)
__device__ __half g_uh[2 * NH];             // tanh hidden u (fp16)
__device__ float  g_vfin[2][NH];            // h after full integration (fp32)
__device__ float  g_g[2][NH];
__device__ float  g_hhat[2][NH];
__device__ float  g_hnew[2][NH];
__device__ float  g_xd[2][NH];
__device__ unsigned g_arrive;               // full-grid barrier (GRU/out only)
__device__ unsigned g_cnt[8 * SL_STRIDE];   // per-slice producer counters

__global__ void k_reset()
{
    if (threadIdx.x == 0) g_arrive = 0u;
    if (threadIdx.x < 8 * SL_STRIDE) g_cnt[threadIdx.x] = 0u;
}

// ------- fp32 -> fp16 + permute to mma A-fragment-major layout --------------
__global__ __launch_bounds__(256)
void k_perm(const float* __restrict__ W, __half* __restrict__ P)
{
    const int gidx = blockIdx.x * 256 + threadIdx.x;   // tile*32 + lane
    const int lane = gidx & 31, tile = gidx >> 5;
    const int rg = tile >> 8, kt = tile & 255;
    const int R0 = rg * 16, C0 = kt * 16;
    const int g = lane >> 2, q = lane & 3;
    const float2* r0p = reinterpret_cast<const float2*>(W + (size_t)(R0 + g)     * NH + C0 + 2*q);
    const float2* r8p = reinterpret_cast<const float2*>(W + (size_t)(R0 + 8 + g) * NH + C0 + 2*q);
    float2 a01 = r0p[0];
    float2 a23 = r8p[0];
    float2 a45 = r0p[4];
    float2 a67 = r8p[4];
    __half2 h0 = __floats2half2_rn(a01.x, a01.y);
    __half2 h1 = __floats2half2_rn(a23.x, a23.y);
    __half2 h2 = __floats2half2_rn(a45.x, a45.y);
    __half2 h3 = __floats2half2_rn(a67.x, a67.y);
    uint4 o;
    o.x = *reinterpret_cast<uint32_t*>(&h0);
    o.y = *reinterpret_cast<uint32_t*>(&h1);
    o.z = *reinterpret_cast<uint32_t*>(&h2);
    o.w = *reinterpret_cast<uint32_t*>(&h3);
    reinterpret_cast<uint4*>(P)[gidx] = o;
}

// ---------------- full-grid barrier (GRU/out phases only) -------------------
__device__ __forceinline__ void bar_arrive()
{
    __syncthreads();
    if (threadIdx.x == 0) {
        unsigned* p = &g_arrive;
        asm volatile("red.release.gpu.global.add.u32 [%0], 1;" :: "l"(p) : "memory");
    }
}
__device__ __forceinline__ void bar_wait(unsigned& target)
{
    if (threadIdx.x == 0) {
        unsigned* p = &g_arrive;
        unsigned v;
        do {
            asm volatile("ld.acquire.gpu.global.u32 %0, [%1];" : "=r"(v) : "l"(p) : "memory");
        } while (v < target);
    }
    __syncthreads();
    target += GRIDB;
}

// ---------------- per-slice producer/consumer sync --------------------------
// Producer (after its 32 output rows are stored + block-synced): +1 on its slice.
__device__ __forceinline__ void slice_arrive()
{
    __syncthreads();                // order all reducers' stores before release
    if (threadIdx.x == 0) {
        unsigned* p = &g_cnt[(blockIdx.x >> 4) * SL_STRIDE];
        asm volatile("red.release.gpu.global.add.u32 [%0], 1;" :: "l"(p) : "memory");
    }
}
// Consumer warp: wait until its slice has all 16 producer arrivals for this phase.
__device__ __forceinline__ void slice_wait(int kc, unsigned tgt)
{
    if ((threadIdx.x & 31) == 0) {
        unsigned* p = &g_cnt[kc * SL_STRIDE];
        unsigned v;
        do {
            asm volatile("ld.acquire.gpu.global.u32 %0, [%1];" : "=r"(v) : "l"(p) : "memory");
        } while (v < tgt);
    }
    __syncwarp();
}

// ---------------- HMMA m16n8k16 fp32-accum ----------------
__device__ __forceinline__ void mma16816(float c[4], const uint4& a,
                                         uint32_t b0, uint32_t b1)
{
    asm volatile(
        "mma.sync.aligned.m16n8k16.row.col.f32.f16.f16.f32 "
        "{%0,%1,%2,%3}, {%4,%5,%6,%7}, {%8,%9}, {%0,%1,%2,%3};"
        : "+f"(c[0]), "+f"(c[1]), "+f"(c[2]), "+f"(c[3])
        : "r"(a.x), "r"(a.y), "r"(a.z), "r"(a.w), "r"(b0), "r"(b1));
}

__device__ __forceinline__ const uint4* a_ptr(const __half* Wp, int warp, int lane)
{
    const int rg = warp >> 3, kc = warp & 7;
    const int rg_glob = blockIdx.x * 2 + rg;
    return reinterpret_cast<const uint4*>(Wp)
         + ((size_t)rg_glob * 256 + kc * 32) * 32 + lane;
}

__device__ __forceinline__ void a_prefetch(uint4* abuf, const uint4* A)
{
    #pragma unroll
    for (int p = 0; p < 8; p++) abuf[p] = A[p * 32];
}

// Per-warp B staging: warp copies its own K-slice (2 x 1 KB) from L2 into its
// private smem region, then syncwarp.
__device__ __forceinline__ void stage_b(__half* __restrict__ swarp,
                                        const __half* __restrict__ gB,
                                        int warp, int lane)
{
    const int kc = warp & 7;
    uint4* dst = reinterpret_cast<uint4*>(swarp);
    #pragma unroll
    for (int b = 0; b < 2; b++) {
        const uint4* src = reinterpret_cast<const uint4*>(gB + b * NH + kc * 512);
        dst[b * 64 + lane]      = __ldcg(src + lane);
        dst[b * 64 + lane + 32] = __ldcg(src + lane + 32);
    }
    __syncwarp();
}

// mma mainloop: ring 8 A-fragments, B from warp-private smem, 2 accum chains.
__device__ __forceinline__ void ode_mma(uint4* abuf, const uint4* A,
                                        const __half* __restrict__ swarp,
                                        float* __restrict__ part,
                                        int warp, int lane)
{
    const int rg = warp >> 3, kc = warp & 7;
    const int n = lane >> 2, q = lane & 3;
    const bool hasB = (n < 2);
    const __half* vb = swarp + (hasB ? n : 0) * 512 + q * 2;

    float c0[4] = {0.f,0.f,0.f,0.f}, c1[4] = {0.f,0.f,0.f,0.f};
    #pragma unroll
    for (int s = 0; s < 32; s++) {
        uint4 a = abuf[s & 7];
        if (s < 24) abuf[s & 7] = A[(size_t)(s + 8) * 32];
        uint32_t b0 = 0u, b1 = 0u;
        if (hasB) {
            b0 = *reinterpret_cast<const uint32_t*>(vb + s * 16);
            b1 = *reinterpret_cast<const uint32_t*>(vb + s * 16 + 8);
        }
        if (s & 1) mma16816(c1, a, b0, b1);
        else       mma16816(c0, a, b0, b1);
    }
    if (q == 0) {
        const int r = rg * 16 + n;
        part[(kc * 32 + r)     * 2 + 0] = c0[0] + c1[0];
        part[(kc * 32 + r)     * 2 + 1] = c0[1] + c1[1];
        part[(kc * 32 + r + 8) * 2 + 0] = c0[2] + c1[2];
        part[(kc * 32 + r + 8) * 2 + 1] = c0[3] + c1[3];
    }
}

// ---------------- fp32 warp dots (GRU / out) ----------------
template<int K4>
__device__ __forceinline__ void wdot_f2(const float4* __restrict__ Wr,
                                        const float4* __restrict__ v0,
                                        const float4* __restrict__ v1,
                                        int lane, float& a0, float& a1)
{
    a0 = 0.f; a1 = 0.f;
    #pragma unroll 8
    for (int i = lane; i < K4; i += 32) {
        float4 w = Wr[i], x0 = v0[i], x1 = v1[i];
        a0 += w.x*x0.x + w.y*x0.y + w.z*x0.z + w.w*x0.w;
        a1 += w.x*x1.x + w.y*x1.y + w.z*x1.z + w.w*x1.w;
    }
    #pragma unroll
    for (int off = 16; off; off >>= 1) {
        a0 += __shfl_down_sync(0xffffffffu, a0, off);
        a1 += __shfl_down_sync(0xffffffffu, a1, off);
    }
}

template<int K4>
__device__ __forceinline__ float wdot_f1(const float4* __restrict__ Wr,
                                         const float4* __restrict__ v, int lane)
{
    float a = 0.f;
    #pragma unroll 8
    for (int i = lane; i < K4; i += 32) {
        float4 w = Wr[i], x = v[i];
        a += w.x*x.x + w.y*x.y + w.z*x.z + w.w*x.w;
    }
    #pragma unroll
    for (int off = 16; off; off >>= 1) a += __shfl_down_sync(0xffffffffu, a, off);
    return a;
}

// ---------------- the whole model in one persistent kernel ------------------
__global__ __launch_bounds__(TPB, 1)
void k_all(const float* __restrict__ f_b1, const float* __restrict__ f_b2,
           const float* __restrict__ i2h_W, const float* __restrict__ i2h_b,
           const float* __restrict__ h2o_W, const float* __restrict__ h2o_b,
           const float* __restrict__ x_f, const float* __restrict__ x_b,
           const float* __restrict__ h_f, const float* __restrict__ h_b,
           const float* __restrict__ tf, const float* __restrict__ tb,
           float* __restrict__ out, int nsteps)
{
    __shared__ __half sB[16][2 * 512];     // 32 KB: per-warp B slices
    __shared__ union {
        float svf[2][NH];                  // 32 KB (GRU / out)
        float part[8 * 32 * 2];            //  2 KB (ODE partials)
    } sm;

    const int tid  = threadIdx.x;
    const int warp = tid >> 5, lane = tid & 31;
    const int kc   = warp & 7;
    unsigned target = GRIDB;               // full barrier target (GRU/out)
    unsigned wtgt   = 16;                  // slice target (per-warp)
    uint4 abuf[8];

    const uint4* A1 = a_ptr(g_W1p, warp, lane);
    const uint4* A2 = a_ptr(g_W2p, warp, lane);

    // ---- reducer persistent state (threads 0..63: row rw, batch b) ----
    const int red_r  = tid >> 1;
    const int red_b  = tid & 1;
    const int red_rw = blockIdx.x * ROWS_PB + red_r;
    float hbase = 0.f, ksumr = 0.f, bias1 = 0.f, bias2 = 0.f;
    if (tid < 64) {
        hbase = (red_b ? h_b : h_f)[red_rw];
        bias1 = f_b1[red_rw];
        bias2 = f_b2[red_rw];
        __stcg(reinterpret_cast<unsigned short*>(&g_vh[red_b * NH + red_rw]),
               __half_as_ushort(__float2half(hbase)));
    }
    slice_arrive();                        // publish initial v slice

    // ---- GRU x-half dot (independent of ODE; overlaps others' init) ----
    for (int j = tid; j < NH; j += TPB) { sm.svf[0][j] = x_f[j]; sm.svf[1][j] = x_b[j]; }
    __syncthreads();
    #pragma unroll
    for (int r2 = 0; r2 < 2; r2++) {
        const int row = blockIdx.x * ROWS_PB + warp * 2 + r2;
        float a0, a1;
        wdot_f2<NH/4>(reinterpret_cast<const float4*>(i2h_W + (size_t)row * K2),
                      reinterpret_cast<const float4*>(sm.svf[0]),
                      reinterpret_cast<const float4*>(sm.svf[1]), lane, a0, a1);
        if (lane == 0) { g_xd[0][row] = a0; g_xd[1][row] = a1; }
    }
    __syncthreads();                       // svf reuse safety before ODE partials
    a_prefetch(abuf, A1);                  // first layer-1 fragments in flight

    // ---- RK4 ODE: 240 matvec phases, slice-synchronized ----
    for (int s = 0; s < nsteps; s++) {
        for (int stage = 0; stage < 4; stage++) {
            // ======== layer 1: u = tanh(W1 @ v + b1) ========
            slice_wait(kc, wtgt); wtgt += 16;
            stage_b(sB[warp], g_vh, warp, lane);
            ode_mma(abuf, A1, sB[warp], sm.part, warp, lane);
            __syncthreads();
            a_prefetch(abuf, A2);          // next matvec's A streams during reduce
            if (tid < 64) {
                float acc = 0.f;
                #pragma unroll
                for (int c = 0; c < 8; c++) acc += sm.part[(c * 32 + red_r) * 2 + red_b];
                const float u = tanhf(acc + bias1);
                __stcg(reinterpret_cast<unsigned short*>(&g_uh[red_b * NH + red_rw]),
                       __half_as_ushort(__float2half(u)));
            }
            slice_arrive();

            // ======== layer 2: k = W2 @ u + b2; RK4 state update ========
            slice_wait(kc, wtgt); wtgt += 16;
            stage_b(sB[warp], g_uh, warp, lane);
            ode_mma(abuf, A2, sB[warp], sm.part, warp, lane);
            __syncthreads();
            a_prefetch(abuf, A1);
            if (tid < 64) {
                float acc = 0.f;
                #pragma unroll
                for (int c = 0; c < 8; c++) acc += sm.part[(c * 32 + red_r) * 2 + red_b];
                const float kv = acc + bias2;
                const float* t = red_b ? tb : tf;
                const float dt = t[s+1] - t[s];
                float vnext;
                if (stage == 0)      { ksumr = kv;           vnext = hbase + 0.5f*dt*kv; }
                else if (stage == 1) { ksumr += 2.f*kv;      vnext = hbase + 0.5f*dt*kv; }
                else if (stage == 2) { ksumr += 2.f*kv;      vnext = hbase + dt*kv; }
                else {
                    ksumr += kv;
                    hbase += (dt * (1.0f/6.0f)) * ksumr;
                    vnext = hbase;
                    if (s == nsteps - 1)
                        __stcg(&g_vfin[red_b][red_rw], hbase);
                }
                __stcg(reinterpret_cast<unsigned short*>(&g_vh[red_b * NH + red_rw]),
                       __half_as_ushort(__float2half(vnext)));
            }
            slice_arrive();
        }
    }

    // ---- GRU phase 0: g = sigmoid(xd + W_h @ h_fin + b) ----
    bar_arrive();
    bar_wait(target);
    {
        const float4* src = reinterpret_cast<const float4*>(&g_vfin[0][0]);
        float4* dst = reinterpret_cast<float4*>(&sm.svf[0][0]);
        #pragma unroll
        for (int r = 0; r < 4; r++) dst[tid + r * TPB] = __ldcg(src + tid + r * TPB);
    }
    __syncthreads();
    #pragma unroll
    for (int r2 = 0; r2 < 2; r2++) {
        const int row = blockIdx.x * ROWS_PB + warp * 2 + r2;
        float a0, a1;
        wdot_f2<NH/4>(reinterpret_cast<const float4*>(i2h_W + (size_t)row * K2 + NH),
                      reinterpret_cast<const float4*>(sm.svf[0]),
                      reinterpret_cast<const float4*>(sm.svf[1]), lane, a0, a1);
        if (lane == 0) {
            const float bb = i2h_b[row];
            __stcg(&g_g[0][row], 1.f / (1.f + expf(-(g_xd[0][row] + a0 + bb))));
            __stcg(&g_g[1][row], 1.f / (1.f + expf(-(g_xd[1][row] + a1 + bb))));
        }
    }
    bar_arrive();

    // ---- GRU phase 1: h_hat = tanh(xd + W_h @ (g .* h_fin) + b) ----
    bar_wait(target);
    #pragma unroll
    for (int b = 0; b < 2; b++)
        for (int j = tid; j < NH; j += TPB)
            sm.svf[b][j] = __ldcg(&g_g[b][j]) * __ldcg(&g_vfin[b][j]);
    __syncthreads();
    #pragma unroll
    for (int r2 = 0; r2 < 2; r2++) {
        const int row = blockIdx.x * ROWS_PB + warp * 2 + r2;
        float a0, a1;
        wdot_f2<NH/4>(reinterpret_cast<const float4*>(i2h_W + (size_t)row * K2 + NH),
                      reinterpret_cast<const float4*>(sm.svf[0]),
                      reinterpret_cast<const float4*>(sm.svf[1]), lane, a0, a1);
        if (lane == 0) {
            const float bb = i2h_b[row];
            __stcg(&g_hhat[0][row], tanhf(g_xd[0][row] + a0 + bb));
            __stcg(&g_hhat[1][row], tanhf(g_xd[1][row] + a1 + bb));
        }
    }
    bar_arrive();

    // ---- GRU blend + emit h_f / h_b ----
    bar_wait(target);
    {
        int i = blockIdx.x * TPB + tid;
        if (i < 2 * NH) {
            const int b = i >> 12, j = i & (NH - 1);
            const float g  = __ldcg(&g_g[b][j]);
            const float hn = g * __ldcg(&g_vfin[b][j]) + (1.f - g) * __ldcg(&g_hhat[b][j]);
            __stcg(&g_hnew[b][j], hn);
            out[NH + i] = hn;
        }
    }
    bar_arrive();

    // ---- output matvec ----
    bar_wait(target);
    {
        const float4* src = reinterpret_cast<const float4*>(&g_hnew[0][0]);
        float4* dst = reinterpret_cast<float4*>(&sm.svf[0][0]);
        #pragma unroll
        for (int r = 0; r < 4; r++) dst[tid + r * TPB] = __ldcg(src + tid + r * TPB);
    }
    __syncthreads();
    #pragma unroll
    for (int r2 = 0; r2 < 2; r2++) {
        const int row = blockIdx.x * ROWS_PB + warp * 2 + r2;
        float a = wdot_f1<K2/4>(reinterpret_cast<const float4*>(h2o_W + (size_t)row * K2),
                                reinterpret_cast<const float4*>(&sm.svf[0][0]), lane);
        if (lane == 0) out[row] = a + h2o_b[row];
    }
}

extern "C" void kernel_launch(void* const* d_in, const int* in_sizes, int n_in,
                              void* d_out, int out_size)
{
    const float* x_f   = (const float*)d_in[0];
    const float* x_b   = (const float*)d_in[1];
    const float* h_f   = (const float*)d_in[2];
    const float* h_b   = (const float*)d_in[3];
    const float* t_f   = (const float*)d_in[4];
    const float* t_b   = (const float*)d_in[5];
    const float* i2h_W = (const float*)d_in[6];
    const float* i2h_b = (const float*)d_in[7];
    const float* h2o_W = (const float*)d_in[8];
    const float* h2o_b = (const float*)d_in[9];
    const float* f_W1  = (const float*)d_in[10];
    const float* f_b1  = (const float*)d_in[11];
    const float* f_W2  = (const float*)d_in[12];
    const float* f_b2  = (const float*)d_in[13];
    float* out = (float*)d_out;

    const int T = in_sizes[4];
    const int nsteps = T - 1;

    __half *w1p, *w2p;
    cudaGetSymbolAddress((void**)&w1p, g_W1p);
    cudaGetSymbolAddress((void**)&w2p, g_W2p);

    const int permBlocks = (NH / 16) * (NH / 16) * 32 / 256;   // 8192
    k_perm<<<permBlocks, 256>>>(f_W1, w1p);
    k_perm<<<permBlocks, 256>>>(f_W2, w2p);
    k_reset<<<1, 256>>>();

    k_all<<<GRIDB, TPB>>>(f_b1, f_b2, i2h_W, i2h_b, h2o_W, h2o_b,
                          x_f, x_b, h_f, h_b, t_f, t_b, out, nsteps);
}

// round 10
// speedup vs baseline: 1.0424x; 1.0424x over previous
#include <cuda_runtime.h>
#include <cuda_fp16.h>
#include <math.h>
#include <stdint.h>

#define NH     4096
#define K2     8192
#define GRIDB  128          // blocks (<= 148 SMs -> co-resident, barrier safe)
#define TPB    512          // 16 warps
#define ROWS_PB 32
#define F_CACHED 12         // A-fragments pinned in smem per warp per matrix
#define G_STREAM (32 - F_CACHED)

// dynamic smem layout (bytes)
#define SW_BYTES  (16 * 2 * F_CACHED * 512)        // 196608: pinned A cache
#define SB_OFF    SW_BYTES                          // 16 KB staged B
#define PART_OFF  (SW_BYTES + 2 * NH * 2)           // 2 KB partials
#define SMEM_TOTAL (PART_OFF + 8 * 32 * 2 * 4)      // 215040

// ---------------- persistent device scratch (no allocations) ----------------
__device__ __half g_W1p[(size_t)NH * NH];   // fp16 f_W1, fragment-major
__device__ __half g_W2p[(size_t)NH * NH];   // fp16 f_W2, fragment-major
__device__ __half g_vh[2 * NH];             // current ODE input vector v (fp16)
__device__ __half g_uh[2 * NH];             // tanh hidden u (fp16)
__device__ float  g_vfin[2][NH];            // h after full integration (fp32)
__device__ float  g_g[2][NH];
__device__ float  g_hhat[2][NH];
__device__ float  g_hnew[2][NH];
__device__ float  g_xd[2][NH];
__device__ unsigned g_arrive;

__global__ void k_reset() { g_arrive = 0u; }

// ------- fp32 -> fp16 + permute to mma A-fragment-major layout --------------
__global__ __launch_bounds__(256)
void k_perm(const float* __restrict__ W, __half* __restrict__ P)
{
    const int gidx = blockIdx.x * 256 + threadIdx.x;   // tile*32 + lane
    const int lane = gidx & 31, tile = gidx >> 5;
    const int rg = tile >> 8, kt = tile & 255;
    const int R0 = rg * 16, C0 = kt * 16;
    const int g = lane >> 2, q = lane & 3;
    const float2* r0p = reinterpret_cast<const float2*>(W + (size_t)(R0 + g)     * NH + C0 + 2*q);
    const float2* r8p = reinterpret_cast<const float2*>(W + (size_t)(R0 + 8 + g) * NH + C0 + 2*q);
    float2 a01 = r0p[0];
    float2 a23 = r8p[0];
    float2 a45 = r0p[4];
    float2 a67 = r8p[4];
    __half2 h0 = __floats2half2_rn(a01.x, a01.y);
    __half2 h1 = __floats2half2_rn(a23.x, a23.y);
    __half2 h2 = __floats2half2_rn(a45.x, a45.y);
    __half2 h3 = __floats2half2_rn(a67.x, a67.y);
    uint4 o;
    o.x = *reinterpret_cast<uint32_t*>(&h0);
    o.y = *reinterpret_cast<uint32_t*>(&h1);
    o.z = *reinterpret_cast<uint32_t*>(&h2);
    o.w = *reinterpret_cast<uint32_t*>(&h3);
    reinterpret_cast<uint4*>(P)[gidx] = o;
}

// ---------------- full-grid barrier: release-red / acquire-poll -------------
__device__ __forceinline__ void bar_arrive()
{
    __syncthreads();
    if (threadIdx.x == 0) {
        unsigned* p = &g_arrive;
        asm volatile("red.release.gpu.global.add.u32 [%0], 1;" :: "l"(p) : "memory");
    }
}
__device__ __forceinline__ void bar_wait(unsigned& target)
{
    if (threadIdx.x == 0) {
        unsigned* p = &g_arrive;
        unsigned v;
        do {
            asm volatile("ld.acquire.gpu.global.u32 %0, [%1];" : "=r"(v) : "l"(p) : "memory");
        } while (v < target);
    }
    __syncthreads();
    target += GRIDB;
}

// ---------------- HMMA m16n8k16 fp32-accum ----------------
__device__ __forceinline__ void mma16816(float c[4], const uint4& a,
                                         uint32_t b0, uint32_t b1)
{
    asm volatile(
        "mma.sync.aligned.m16n8k16.row.col.f32.f16.f16.f32 "
        "{%0,%1,%2,%3}, {%4,%5,%6,%7}, {%8,%9}, {%0,%1,%2,%3};"
        : "+f"(c[0]), "+f"(c[1]), "+f"(c[2]), "+f"(c[3])
        : "r"(a.x), "r"(a.y), "r"(a.z), "r"(a.w), "r"(b0), "r"(b1));
}

__device__ __forceinline__ const uint4* a_ptr(const __half* Wp, int warp, int lane)
{
    const int rg = warp >> 3, kc = warp & 7;
    const int rg_glob = blockIdx.x * 2 + rg;
    return reinterpret_cast<const uint4*>(Wp)
         + ((size_t)rg_glob * 256 + kc * 32) * 32 + lane;
}

__device__ __forceinline__ void a_prefetch(uint4* abuf, const uint4* Ag)
{
    #pragma unroll
    for (int p = 0; p < 8; p++) abuf[p] = Ag[p * 32];
}

// mma mainloop: F_CACHED steps from pinned smem, G_STREAM steps via global ring.
__device__ __forceinline__ void ode_mma(uint4* abuf, const uint4* Ag,
                                        const uint4* __restrict__ sWm,
                                        const __half* __restrict__ sB,
                                        float* __restrict__ part,
                                        int warp, int lane)
{
    const int rg = warp >> 3, kc = warp & 7;
    const int n = lane >> 2, q = lane & 3;
    const bool hasB = (n < 2);
    const __half* vb = sB + (hasB ? n : 0) * NH + kc * 512 + q * 2;

    float c0[4] = {0.f,0.f,0.f,0.f}, c1[4] = {0.f,0.f,0.f,0.f};
    // pinned-smem steps (global ring loads land meanwhile)
    #pragma unroll
    for (int s = 0; s < F_CACHED; s++) {
        uint4 a = sWm[s * 32 + lane];
        uint32_t b0 = 0u, b1 = 0u;
        if (hasB) {
            b0 = *reinterpret_cast<const uint32_t*>(vb + s * 16);
            b1 = *reinterpret_cast<const uint32_t*>(vb + s * 16 + 8);
        }
        if (s & 1) mma16816(c1, a, b0, b1);
        else       mma16816(c0, a, b0, b1);
    }
    // streamed steps
    #pragma unroll
    for (int g = 0; g < G_STREAM; g++) {
        uint4 a = abuf[g & 7];
        if (g < G_STREAM - 8) abuf[g & 7] = Ag[(size_t)(g + 8) * 32];
        const int s = F_CACHED + g;
        uint32_t b0 = 0u, b1 = 0u;
        if (hasB) {
            b0 = *reinterpret_cast<const uint32_t*>(vb + s * 16);
            b1 = *reinterpret_cast<const uint32_t*>(vb + s * 16 + 8);
        }
        if (s & 1) mma16816(c1, a, b0, b1);
        else       mma16816(c0, a, b0, b1);
    }
    if (q == 0) {
        const int r = rg * 16 + n;
        part[(kc * 32 + r)     * 2 + 0] = c0[0] + c1[0];
        part[(kc * 32 + r)     * 2 + 1] = c0[1] + c1[1];
        part[(kc * 32 + r + 8) * 2 + 0] = c0[2] + c1[2];
        part[(kc * 32 + r + 8) * 2 + 1] = c0[3] + c1[3];
    }
}

// ---------------- fp32 warp dots (GRU / out) ----------------
template<int K4>
__device__ __forceinline__ void wdot_f2(const float4* __restrict__ Wr,
                                        const float4* __restrict__ v0,
                                        const float4* __restrict__ v1,
                                        int lane, float& a0, float& a1)
{
    a0 = 0.f; a1 = 0.f;
    #pragma unroll 8
    for (int i = lane; i < K4; i += 32) {
        float4 w = Wr[i], x0 = v0[i], x1 = v1[i];
        a0 += w.x*x0.x + w.y*x0.y + w.z*x0.z + w.w*x0.w;
        a1 += w.x*x1.x + w.y*x1.y + w.z*x1.z + w.w*x1.w;
    }
    #pragma unroll
    for (int off = 16; off; off >>= 1) {
        a0 += __shfl_down_sync(0xffffffffu, a0, off);
        a1 += __shfl_down_sync(0xffffffffu, a1, off);
    }
}

template<int K4>
__device__ __forceinline__ float wdot_f1(const float4* __restrict__ Wr,
                                         const float4* __restrict__ v, int lane)
{
    float a = 0.f;
    #pragma unroll 8
    for (int i = lane; i < K4; i += 32) {
        float4 w = Wr[i], x = v[i];
        a += w.x*x.x + w.y*x.y + w.z*x.z + w.w*x.w;
    }
    #pragma unroll
    for (int off = 16; off; off >>= 1) a += __shfl_down_sync(0xffffffffu, a, off);
    return a;
}

// ---------------- the whole model in one persistent kernel ------------------
__global__ __launch_bounds__(TPB, 1)
void k_all(const float* __restrict__ f_b1, const float* __restrict__ f_b2,
           const float* __restrict__ i2h_W, const float* __restrict__ i2h_b,
           const float* __restrict__ h2o_W, const float* __restrict__ h2o_b,
           const float* __restrict__ x_f, const float* __restrict__ x_b,
           const float* __restrict__ h_f, const float* __restrict__ h_b,
           const float* __restrict__ tf, const float* __restrict__ tb,
           float* __restrict__ out, int nsteps)
{
    extern __shared__ unsigned char smem_dyn[];
    uint4*  sW   = reinterpret_cast<uint4*>(smem_dyn);                 // 192 KB
    __half* sB   = reinterpret_cast<__half*>(smem_dyn + SB_OFF);       //  16 KB
    float*  part = reinterpret_cast<float*>(smem_dyn + PART_OFF);      //   2 KB
    float*  svf  = reinterpret_cast<float*>(smem_dyn);                 // GRU alias

    const int tid  = threadIdx.x;
    const int warp = tid >> 5, lane = tid & 31;
    unsigned target = GRIDB;
    uint4 abuf[8];

    const uint4* A1g = a_ptr(g_W1p, warp, lane) + F_CACHED * 32;   // streamed tail
    const uint4* A2g = a_ptr(g_W2p, warp, lane) + F_CACHED * 32;
    uint4* sW1 = sW + (warp * 2 + 0) * (F_CACHED * 32);
    uint4* sW2 = sW + (warp * 2 + 1) * (F_CACHED * 32);

    // ---- reducer persistent state (threads 0..63: row rw, batch b) ----
    const int red_r  = tid >> 1;
    const int red_b  = tid & 1;
    const int red_rw = blockIdx.x * ROWS_PB + red_r;
    float hbase = 0.f, ksumr = 0.f, bias1 = 0.f, bias2 = 0.f;
    if (tid < 64) {
        hbase = (red_b ? h_b : h_f)[red_rw];
        bias1 = f_b1[red_rw];
        bias2 = f_b2[red_rw];
        __stcg(reinterpret_cast<unsigned short*>(&g_vh[red_b * NH + red_rw]),
               __half_as_ushort(__float2half(hbase)));
    }

    // ---- GRU x-half dot (independent of ODE) ----
    for (int j = tid; j < NH; j += TPB) { svf[j] = x_f[j]; svf[NH + j] = x_b[j]; }
    __syncthreads();
    #pragma unroll
    for (int r2 = 0; r2 < 2; r2++) {
        const int row = blockIdx.x * ROWS_PB + warp * 2 + r2;
        float a0, a1;
        wdot_f2<NH/4>(reinterpret_cast<const float4*>(i2h_W + (size_t)row * K2),
                      reinterpret_cast<const float4*>(svf),
                      reinterpret_cast<const float4*>(svf + NH), lane, a0, a1);
        if (lane == 0) { g_xd[0][row] = a0; g_xd[1][row] = a1; }
    }
    __syncthreads();

    // ---- pin first F_CACHED A-fragments of both matrices in smem (once) ----
    {
        const uint4* A1f = a_ptr(g_W1p, warp, lane);
        const uint4* A2f = a_ptr(g_W2p, warp, lane);
        #pragma unroll
        for (int f = 0; f < F_CACHED; f++) {
            sW1[f * 32 + lane] = A1f[(size_t)f * 32];
            sW2[f * 32 + lane] = A2f[(size_t)f * 32];
        }
    }
    a_prefetch(abuf, A1g);
    bar_arrive();

    // ---- RK4 ODE: 120 phases ----
    for (int s = 0; s < nsteps; s++) {
        for (int stage = 0; stage < 4; stage++) {
            // ======== layer 1: u = tanh(W1 @ v + b1) ========
            bar_wait(target);
            {
                const uint4* src = reinterpret_cast<const uint4*>(&g_vh[0]);
                uint4* dst = reinterpret_cast<uint4*>(sB);
                dst[tid]       = __ldcg(src + tid);
                dst[tid + TPB] = __ldcg(src + tid + TPB);
            }
            __syncthreads();
            ode_mma(abuf, A1g, sW1, sB, part, warp, lane);
            __syncthreads();
            a_prefetch(abuf, A2g);
            if (tid < 64) {
                float acc = 0.f;
                #pragma unroll
                for (int c = 0; c < 8; c++) acc += part[(c * 32 + red_r) * 2 + red_b];
                const float u = tanhf(acc + bias1);
                __stcg(reinterpret_cast<unsigned short*>(&g_uh[red_b * NH + red_rw]),
                       __half_as_ushort(__float2half(u)));
            }
            bar_arrive();

            // ======== layer 2: k = W2 @ u + b2; RK4 state update ========
            bar_wait(target);
            {
                const uint4* src = reinterpret_cast<const uint4*>(&g_uh[0]);
                uint4* dst = reinterpret_cast<uint4*>(sB);
                dst[tid]       = __ldcg(src + tid);
                dst[tid + TPB] = __ldcg(src + tid + TPB);
            }
            __syncthreads();
            ode_mma(abuf, A2g, sW2, sB, part, warp, lane);
            __syncthreads();
            a_prefetch(abuf, A1g);
            if (tid < 64) {
                float acc = 0.f;
                #pragma unroll
                for (int c = 0; c < 8; c++) acc += part[(c * 32 + red_r) * 2 + red_b];
                const float kv = acc + bias2;
                const float* t = red_b ? tb : tf;
                const float dt = t[s+1] - t[s];
                float vnext;
                if (stage == 0)      { ksumr = kv;           vnext = hbase + 0.5f*dt*kv; }
                else if (stage == 1) { ksumr += 2.f*kv;      vnext = hbase + 0.5f*dt*kv; }
                else if (stage == 2) { ksumr += 2.f*kv;      vnext = hbase + dt*kv; }
                else {
                    ksumr += kv;
                    hbase += (dt * (1.0f/6.0f)) * ksumr;
                    vnext = hbase;
                    if (s == nsteps - 1)
                        __stcg(&g_vfin[red_b][red_rw], hbase);
                }
                __stcg(reinterpret_cast<unsigned short*>(&g_vh[red_b * NH + red_rw]),
                       __half_as_ushort(__float2half(vnext)));
            }
            bar_arrive();
        }
    }

    // ---- GRU phase 0: g = sigmoid(xd + W_h @ h_fin + b) ----
    bar_wait(target);
    {
        const float4* src = reinterpret_cast<const float4*>(&g_vfin[0][0]);
        float4* dst = reinterpret_cast<float4*>(svf);
        #pragma unroll
        for (int r = 0; r < 4; r++) dst[tid + r * TPB] = __ldcg(src + tid + r * TPB);
    }
    __syncthreads();
    #pragma unroll
    for (int r2 = 0; r2 < 2; r2++) {
        const int row = blockIdx.x * ROWS_PB + warp * 2 + r2;
        float a0, a1;
        wdot_f2<NH/4>(reinterpret_cast<const float4*>(i2h_W + (size_t)row * K2 + NH),
                      reinterpret_cast<const float4*>(svf),
                      reinterpret_cast<const float4*>(svf + NH), lane, a0, a1);
        if (lane == 0) {
            const float bb = i2h_b[row];
            __stcg(&g_g[0][row], 1.f / (1.f + expf(-(g_xd[0][row] + a0 + bb))));
            __stcg(&g_g[1][row], 1.f / (1.f + expf(-(g_xd[1][row] + a1 + bb))));
        }
    }
    bar_arrive();

    // ---- GRU phase 1: h_hat = tanh(xd + W_h @ (g .* h_fin) + b) ----
    bar_wait(target);
    for (int j = tid; j < NH; j += TPB) {
        svf[j]      = __ldcg(&g_g[0][j]) * __ldcg(&g_vfin[0][j]);
        svf[NH + j] = __ldcg(&g_g[1][j]) * __ldcg(&g_vfin[1][j]);
    }
    __syncthreads();
    #pragma unroll
    for (int r2 = 0; r2 < 2; r2++) {
        const int row = blockIdx.x * ROWS_PB + warp * 2 + r2;
        float a0, a1;
        wdot_f2<NH/4>(reinterpret_cast<const float4*>(i2h_W + (size_t)row * K2 + NH),
                      reinterpret_cast<const float4*>(svf),
                      reinterpret_cast<const float4*>(svf + NH), lane, a0, a1);
        if (lane == 0) {
            const float bb = i2h_b[row];
            __stcg(&g_hhat[0][row], tanhf(g_xd[0][row] + a0 + bb));
            __stcg(&g_hhat[1][row], tanhf(g_xd[1][row] + a1 + bb));
        }
    }
    bar_arrive();

    // ---- GRU blend + emit h_f / h_b ----
    bar_wait(target);
    {
        int i = blockIdx.x * TPB + tid;
        if (i < 2 * NH) {
            const int b = i >> 12, j = i & (NH - 1);
            const float g  = __ldcg(&g_g[b][j]);
            const float hn = g * __ldcg(&g_vfin[b][j]) + (1.f - g) * __ldcg(&g_hhat[b][j]);
            __stcg(&g_hnew[b][j], hn);
            out[NH + i] = hn;
        }
    }
    bar_arrive();

    // ---- output matvec ----
    bar_wait(target);
    {
        const float4* src = reinterpret_cast<const float4*>(&g_hnew[0][0]);
        float4* dst = reinterpret_cast<float4*>(svf);
        #pragma unroll
        for (int r = 0; r < 4; r++) dst[tid + r * TPB] = __ldcg(src + tid + r * TPB);
    }
    __syncthreads();
    #pragma unroll
    for (int r2 = 0; r2 < 2; r2++) {
        const int row = blockIdx.x * ROWS_PB + warp * 2 + r2;
        float a = wdot_f1<K2/4>(reinterpret_cast<const float4*>(h2o_W + (size_t)row * K2),
                                reinterpret_cast<const float4*>(svf), lane);
        if (lane == 0) out[row] = a + h2o_b[row];
    }
}

extern "C" void kernel_launch(void* const* d_in, const int* in_sizes, int n_in,
                              void* d_out, int out_size)
{
    const float* x_f   = (const float*)d_in[0];
    const float* x_b   = (const float*)d_in[1];
    const float* h_f   = (const float*)d_in[2];
    const float* h_b   = (const float*)d_in[3];
    const float* t_f   = (const float*)d_in[4];
    const float* t_b   = (const float*)d_in[5];
    const float* i2h_W = (const float*)d_in[6];
    const float* i2h_b = (const float*)d_in[7];
    const float* h2o_W = (const float*)d_in[8];
    const float* h2o_b = (const float*)d_in[9];
    const float* f_W1  = (const float*)d_in[10];
    const float* f_b1  = (const float*)d_in[11];
    const float* f_W2  = (const float*)d_in[12];
    const float* f_b2  = (const float*)d_in[13];
    float* out = (float*)d_out;

    const int T = in_sizes[4];
    const int nsteps = T - 1;

    __half *w1p, *w2p;
    cudaGetSymbolAddress((void**)&w1p, g_W1p);
    cudaGetSymbolAddress((void**)&w2p, g_W2p);

    cudaFuncSetAttribute((const void*)k_all,
                         cudaFuncAttributeMaxDynamicSharedMemorySize, SMEM_TOTAL);

    const int permBlocks = (NH / 16) * (NH / 16) * 32 / 256;   // 8192
    k_perm<<<permBlocks, 256>>>(f_W1, w1p);
    k_perm<<<permBlocks, 256>>>(f_W2, w2p);
    k_reset<<<1, 1>>>();

    k_all<<<GRIDB, TPB, SMEM_TOTAL>>>(f_b1, f_b2, i2h_W, i2h_b, h2o_W, h2o_b,
                                      x_f, x_b, h_f, h_b, t_f, t_b, out, nsteps);
}

// round 11
// speedup vs baseline: 1.0756x; 1.0318x over previous
#include <cuda_runtime.h>
#include <cuda_fp16.h>
#include <math.h>
#include <stdint.h>

#define NH     4096
#define K2     8192
#define GRIDB  128          // blocks (<= 148 SMs -> co-resident, barrier safe)
#define TPB    1024         // 32 warps: rg 2 x kc 16
#define ROWS_PB 32
#define NSTEP  16           // mma K-steps per warp (K=256)
#define RING   4

// ---------------- persistent device scratch (no allocations) ----------------
__device__ __half g_W1p[(size_t)NH * NH];   // fp16 f_W1, fragment-major
__device__ __half g_W2p[(size_t)NH * NH];   // fp16 f_W2, fragment-major
__device__ __half g_vh[2 * NH];             // current ODE input vector v (fp16)
__device__ __half g_uh[2 * NH];             // tanh hidden u (fp16)
__device__ float  g_vfin[2][NH];            // h after full integration (fp32)
__device__ float  g_g[2][NH];
__device__ float  g_hhat[2][NH];
__device__ float  g_hnew[2][NH];
__device__ float  g_xd[2][NH];
__device__ unsigned g_arrive;

__global__ void k_reset() { g_arrive = 0u; }

// ------- fp32 -> fp16 + permute to mma A-fragment-major layout --------------
__global__ __launch_bounds__(256)
void k_perm(const float* __restrict__ W, __half* __restrict__ P)
{
    const int gidx = blockIdx.x * 256 + threadIdx.x;   // tile*32 + lane
    const int lane = gidx & 31, tile = gidx >> 5;
    const int rg = tile >> 8, kt = tile & 255;
    const int R0 = rg * 16, C0 = kt * 16;
    const int g = lane >> 2, q = lane & 3;
    const float2* r0p = reinterpret_cast<const float2*>(W + (size_t)(R0 + g)     * NH + C0 + 2*q);
    const float2* r8p = reinterpret_cast<const float2*>(W + (size_t)(R0 + 8 + g) * NH + C0 + 2*q);
    float2 a01 = r0p[0];
    float2 a23 = r8p[0];
    float2 a45 = r0p[4];
    float2 a67 = r8p[4];
    __half2 h0 = __floats2half2_rn(a01.x, a01.y);
    __half2 h1 = __floats2half2_rn(a23.x, a23.y);
    __half2 h2 = __floats2half2_rn(a45.x, a45.y);
    __half2 h3 = __floats2half2_rn(a67.x, a67.y);
    uint4 o;
    o.x = *reinterpret_cast<uint32_t*>(&h0);
    o.y = *reinterpret_cast<uint32_t*>(&h1);
    o.z = *reinterpret_cast<uint32_t*>(&h2);
    o.w = *reinterpret_cast<uint32_t*>(&h3);
    reinterpret_cast<uint4*>(P)[gidx] = o;
}

// ---------------- full-grid barrier: release-red / acquire-poll -------------
__device__ __forceinline__ void bar_arrive()
{
    __syncthreads();
    if (threadIdx.x == 0) {
        unsigned* p = &g_arrive;
        asm volatile("red.release.gpu.global.add.u32 [%0], 1;" :: "l"(p) : "memory");
    }
}
__device__ __forceinline__ void bar_wait(unsigned& target)
{
    if (threadIdx.x == 0) {
        unsigned* p = &g_arrive;
        unsigned v;
        do {
            asm volatile("ld.acquire.gpu.global.u32 %0, [%1];" : "=r"(v) : "l"(p) : "memory");
        } while (v < target);
    }
    __syncthreads();
    target += GRIDB;
}

// ---------------- HMMA m16n8k16 fp32-accum ----------------
__device__ __forceinline__ void mma16816(float c[4], const uint4& a,
                                         uint32_t b0, uint32_t b1)
{
    asm volatile(
        "mma.sync.aligned.m16n8k16.row.col.f32.f16.f16.f32 "
        "{%0,%1,%2,%3}, {%4,%5,%6,%7}, {%8,%9}, {%0,%1,%2,%3};"
        : "+f"(c[0]), "+f"(c[1]), "+f"(c[2]), "+f"(c[3])
        : "r"(a.x), "r"(a.y), "r"(a.z), "r"(a.w), "r"(b0), "r"(b1));
}

// 32 warps = 2 rg x 16 kc, 16 ktiles each
__device__ __forceinline__ const uint4* a_ptr(const __half* Wp, int warp, int lane)
{
    const int rg = warp >> 4, kc = warp & 15;
    const int rg_glob = blockIdx.x * 2 + rg;
    return reinterpret_cast<const uint4*>(Wp)
         + ((size_t)rg_glob * 256 + kc * NSTEP) * 32 + lane;
}

__device__ __forceinline__ void a_prefetch(uint4* abuf, const uint4* Ag)
{
    #pragma unroll
    for (int p = 0; p < RING; p++) abuf[p] = Ag[p * 32];
}

// mma mainloop: ring-4 A-fragments, B from block-staged smem, 2 accum chains.
__device__ __forceinline__ void ode_mma(uint4* abuf, const uint4* Ag,
                                        const __half* __restrict__ sB,
                                        float* __restrict__ part,
                                        int warp, int lane)
{
    const int rg = warp >> 4, kc = warp & 15;
    const int n = lane >> 2, q = lane & 3;
    const bool hasB = (n < 2);
    const __half* vb = sB + (hasB ? n : 0) * NH + kc * 256 + q * 2;

    float c0[4] = {0.f,0.f,0.f,0.f}, c1[4] = {0.f,0.f,0.f,0.f};
    #pragma unroll
    for (int s = 0; s < NSTEP; s++) {
        uint4 a = abuf[s & (RING-1)];
        if (s < NSTEP - RING) abuf[s & (RING-1)] = Ag[(size_t)(s + RING) * 32];
        uint32_t b0 = 0u, b1 = 0u;
        if (hasB) {
            b0 = *reinterpret_cast<const uint32_t*>(vb + s * 16);
            b1 = *reinterpret_cast<const uint32_t*>(vb + s * 16 + 8);
        }
        if (s & 1) mma16816(c1, a, b0, b1);
        else       mma16816(c0, a, b0, b1);
    }
    if (q == 0) {
        const int r = rg * 16 + n;
        part[(kc * 32 + r)     * 2 + 0] = c0[0] + c1[0];
        part[(kc * 32 + r)     * 2 + 1] = c0[1] + c1[1];
        part[(kc * 32 + r + 8) * 2 + 0] = c0[2] + c1[2];
        part[(kc * 32 + r + 8) * 2 + 1] = c0[3] + c1[3];
    }
}

// ---------------- fp32 warp dots (GRU / out) ----------------
template<int K4>
__device__ __forceinline__ void wdot_f2(const float4* __restrict__ Wr,
                                        const float4* __restrict__ v0,
                                        const float4* __restrict__ v1,
                                        int lane, float& a0, float& a1)
{
    a0 = 0.f; a1 = 0.f;
    #pragma unroll 4
    for (int i = lane; i < K4; i += 32) {
        float4 w = Wr[i], x0 = v0[i], x1 = v1[i];
        a0 += w.x*x0.x + w.y*x0.y + w.z*x0.z + w.w*x0.w;
        a1 += w.x*x1.x + w.y*x1.y + w.z*x1.z + w.w*x1.w;
    }
    #pragma unroll
    for (int off = 16; off; off >>= 1) {
        a0 += __shfl_down_sync(0xffffffffu, a0, off);
        a1 += __shfl_down_sync(0xffffffffu, a1, off);
    }
}

template<int K4>
__device__ __forceinline__ float wdot_f1(const float4* __restrict__ Wr,
                                         const float4* __restrict__ v, int lane)
{
    float a = 0.f;
    #pragma unroll 4
    for (int i = lane; i < K4; i += 32) {
        float4 w = Wr[i], x = v[i];
        a += w.x*x.x + w.y*x.y + w.z*x.z + w.w*x.w;
    }
    #pragma unroll
    for (int off = 16; off; off >>= 1) a += __shfl_down_sync(0xffffffffu, a, off);
    return a;
}

// ---------------- the whole model in one persistent kernel ------------------
__global__ __launch_bounds__(TPB, 1)
void k_all(const float* __restrict__ f_b1, const float* __restrict__ f_b2,
           const float* __restrict__ i2h_W, const float* __restrict__ i2h_b,
           const float* __restrict__ h2o_W, const float* __restrict__ h2o_b,
           const float* __restrict__ x_f, const float* __restrict__ x_b,
           const float* __restrict__ h_f, const float* __restrict__ h_b,
           const float* __restrict__ tf, const float* __restrict__ tb,
           float* __restrict__ out, int nsteps)
{
    __shared__ __half sB[2 * NH];          // 16 KB staged B
    __shared__ union {
        float svf[2][NH];                  // 32 KB (GRU / out)
        float part[16 * 32 * 2];           //  4 KB (ODE partials)
    } sm;

    const int tid  = threadIdx.x;
    const int warp = tid >> 5, lane = tid & 31;
    unsigned target = GRIDB;
    uint4 abuf[RING];

    const uint4* A1 = a_ptr(g_W1p, warp, lane);
    const uint4* A2 = a_ptr(g_W2p, warp, lane);

    // ---- reducer persistent state (threads 0..63: row rw, batch b) ----
    const int red_r  = tid >> 1;
    const int red_b  = tid & 1;
    const int red_rw = blockIdx.x * ROWS_PB + red_r;
    float hbase = 0.f, ksumr = 0.f, bias1 = 0.f, bias2 = 0.f;
    if (tid < 64) {
        hbase = (red_b ? h_b : h_f)[red_rw];
        bias1 = f_b1[red_rw];
        bias2 = f_b2[red_rw];
        __stcg(reinterpret_cast<unsigned short*>(&g_vh[red_b * NH + red_rw]),
               __half_as_ushort(__float2half(hbase)));
    }

    // ---- GRU x-half dot (independent of ODE): one row per warp ----
    for (int j = tid; j < NH; j += TPB) { sm.svf[0][j] = x_f[j]; sm.svf[1][j] = x_b[j]; }
    __syncthreads();
    {
        const int row = blockIdx.x * ROWS_PB + warp;
        float a0, a1;
        wdot_f2<NH/4>(reinterpret_cast<const float4*>(i2h_W + (size_t)row * K2),
                      reinterpret_cast<const float4*>(sm.svf[0]),
                      reinterpret_cast<const float4*>(sm.svf[1]), lane, a0, a1);
        if (lane == 0) { g_xd[0][row] = a0; g_xd[1][row] = a1; }
    }
    __syncthreads();
    a_prefetch(abuf, A1);
    bar_arrive();

    // ---- RK4 ODE: 120 matvec phases ----
    for (int s = 0; s < nsteps; s++) {
        for (int stage = 0; stage < 4; stage++) {
            // ======== layer 1: u = tanh(W1 @ v + b1) ========
            bar_wait(target);
            reinterpret_cast<uint4*>(sB)[tid] =
                __ldcg(reinterpret_cast<const uint4*>(&g_vh[0]) + tid);
            __syncthreads();
            ode_mma(abuf, A1, sB, sm.part, warp, lane);
            __syncthreads();
            a_prefetch(abuf, A2);          // next matvec's A streams during reduce
            if (tid < 64) {
                float acc = 0.f;
                #pragma unroll
                for (int c = 0; c < 16; c++) acc += sm.part[(c * 32 + red_r) * 2 + red_b];
                const float u = tanhf(acc + bias1);
                __stcg(reinterpret_cast<unsigned short*>(&g_uh[red_b * NH + red_rw]),
                       __half_as_ushort(__float2half(u)));
            }
            bar_arrive();

            // ======== layer 2: k = W2 @ u + b2; RK4 state update ========
            bar_wait(target);
            reinterpret_cast<uint4*>(sB)[tid] =
                __ldcg(reinterpret_cast<const uint4*>(&g_uh[0]) + tid);
            __syncthreads();
            ode_mma(abuf, A2, sB, sm.part, warp, lane);
            __syncthreads();
            a_prefetch(abuf, A1);
            if (tid < 64) {
                float acc = 0.f;
                #pragma unroll
                for (int c = 0; c < 16; c++) acc += sm.part[(c * 32 + red_r) * 2 + red_b];
                const float kv = acc + bias2;
                const float* t = red_b ? tb : tf;
                const float dt = t[s+1] - t[s];
                float vnext;
                if (stage == 0)      { ksumr = kv;           vnext = hbase + 0.5f*dt*kv; }
                else if (stage == 1) { ksumr += 2.f*kv;      vnext = hbase + 0.5f*dt*kv; }
                else if (stage == 2) { ksumr += 2.f*kv;      vnext = hbase + dt*kv; }
                else {
                    ksumr += kv;
                    hbase += (dt * (1.0f/6.0f)) * ksumr;
                    vnext = hbase;
                    if (s == nsteps - 1)
                        __stcg(&g_vfin[red_b][red_rw], hbase);
                }
                __stcg(reinterpret_cast<unsigned short*>(&g_vh[red_b * NH + red_rw]),
                       __half_as_ushort(__float2half(vnext)));
            }
            bar_arrive();
        }
    }

    // ---- GRU phase 0: g = sigmoid(xd + W_h @ h_fin + b) ----
    bar_wait(target);
    {
        const float4* src = reinterpret_cast<const float4*>(&g_vfin[0][0]);
        float4* dst = reinterpret_cast<float4*>(&sm.svf[0][0]);
        #pragma unroll
        for (int r = 0; r < 2; r++) dst[tid + r * TPB] = __ldcg(src + tid + r * TPB);
    }
    __syncthreads();
    {
        const int row = blockIdx.x * ROWS_PB + warp;
        float a0, a1;
        wdot_f2<NH/4>(reinterpret_cast<const float4*>(i2h_W + (size_t)row * K2 + NH),
                      reinterpret_cast<const float4*>(sm.svf[0]),
                      reinterpret_cast<const float4*>(sm.svf[1]), lane, a0, a1);
        if (lane == 0) {
            const float bb = i2h_b[row];
            __stcg(&g_g[0][row], 1.f / (1.f + expf(-(g_xd[0][row] + a0 + bb))));
            __stcg(&g_g[1][row], 1.f / (1.f + expf(-(g_xd[1][row] + a1 + bb))));
        }
    }
    bar_arrive();

    // ---- GRU phase 1: h_hat = tanh(xd + W_h @ (g .* h_fin) + b) ----
    bar_wait(target);
    for (int j = tid; j < NH; j += TPB) {
        sm.svf[0][j] = __ldcg(&g_g[0][j]) * __ldcg(&g_vfin[0][j]);
        sm.svf[1][j] = __ldcg(&g_g[1][j]) * __ldcg(&g_vfin[1][j]);
    }
    __syncthreads();
    {
        const int row = blockIdx.x * ROWS_PB + warp;
        float a0, a1;
        wdot_f2<NH/4>(reinterpret_cast<const float4*>(i2h_W + (size_t)row * K2 + NH),
                      reinterpret_cast<const float4*>(sm.svf[0]),
                      reinterpret_cast<const float4*>(sm.svf[1]), lane, a0, a1);
        if (lane == 0) {
            const float bb = i2h_b[row];
            __stcg(&g_hhat[0][row], tanhf(g_xd[0][row] + a0 + bb));
            __stcg(&g_hhat[1][row], tanhf(g_xd[1][row] + a1 + bb));
        }
    }
    bar_arrive();

    // ---- GRU blend + emit h_f / h_b ----
    bar_wait(target);
    {
        int i = blockIdx.x * (2 * NH / GRIDB) + tid;   // 64 elems per block
        if (tid < 2 * NH / GRIDB) {
            const int b = i >> 12, j = i & (NH - 1);
            const float g  = __ldcg(&g_g[b][j]);
            const float hn = g * __ldcg(&g_vfin[b][j]) + (1.f - g) * __ldcg(&g_hhat[b][j]);
            __stcg(&g_hnew[b][j], hn);
            out[NH + i] = hn;
        }
    }
    bar_arrive();

    // ---- output matvec ----
    bar_wait(target);
    {
        const float4* src = reinterpret_cast<const float4*>(&g_hnew[0][0]);
        float4* dst = reinterpret_cast<float4*>(&sm.svf[0][0]);
        #pragma unroll
        for (int r = 0; r < 2; r++) dst[tid + r * TPB] = __ldcg(src + tid + r * TPB);
    }
    __syncthreads();
    {
        const int row = blockIdx.x * ROWS_PB + warp;
        float a = wdot_f1<K2/4>(reinterpret_cast<const float4*>(h2o_W + (size_t)row * K2),
                                reinterpret_cast<const float4*>(&sm.svf[0][0]), lane);
        if (lane == 0) out[row] = a + h2o_b[row];
    }
}

extern "C" void kernel_launch(void* const* d_in, const int* in_sizes, int n_in,
                              void* d_out, int out_size)
{
    const float* x_f   = (const float*)d_in[0];
    const float* x_b   = (const float*)d_in[1];
    const float* h_f   = (const float*)d_in[2];
    const float* h_b   = (const float*)d_in[3];
    const float* t_f   = (const float*)d_in[4];
    const float* t_b   = (const float*)d_in[5];
    const float* i2h_W = (const float*)d_in[6];
    const float* i2h_b = (const float*)d_in[7];
    const float* h2o_W = (const float*)d_in[8];
    const float* h2o_b = (const float*)d_in[9];
    const float* f_W1  = (const float*)d_in[10];
    const float* f_b1  = (const float*)d_in[11];
    const float* f_W2  = (const float*)d_in[12];
    const float* f_b2  = (const float*)d_in[13];
    float* out = (float*)d_out;

    const int T = in_sizes[4];
    const int nsteps = T - 1;

    __half *w1p, *w2p;
    cudaGetSymbolAddress((void**)&w1p, g_W1p);
    cudaGetSymbolAddress((void**)&w2p, g_W2p);

    const int permBlocks = (NH / 16) * (NH / 16) * 32 / 256;   // 8192
    k_perm<<<permBlocks, 256>>>(f_W1, w1p);
    k_perm<<<permBlocks, 256>>>(f_W2, w2p);
    k_reset<<<1, 1>>>();

    k_all<<<GRIDB, TPB>>>(f_b1, f_b2, i2h_W, i2h_b, h2o_W, h2o_b,
                          x_f, x_b, h_f, h_b, t_f, t_b, out, nsteps);
}